// round 6
// baseline (speedup 1.0000x reference)
#include <cuda_runtime.h>
#include <math.h>

namespace {
constexpr int B_ = 64, S_ = 512, I_ = 768, H_ = 512, G4 = 2048;
constexpr int BM = 128, BN = 64, BK = 32, NTILE = I_ / BK;
constexpr int HS_LD = 516;
// hs + Ws + partials(256*2*4 ull) + gb + cs
constexpr int REC_SMEM = (64 * HS_LD + 512 * 32 + 256 * 2 * 4 * 2 + 64 * 32 + 512) * 4;
constexpr int GEMM_SMEM = (2 * BM * 36 + 2 * BK * 72) * 4;
}

__device__ float g_xp[2][(size_t)S_ * B_ * G4];
__device__ float g_h[2][2][B_ * H_];
__device__ unsigned g_cnt[2], g_gen2[2];

__global__ void init_sync_kernel() {
    g_cnt[0] = g_cnt[1] = 0u;
    g_gen2[0] = g_gen2[1] = 0u;
}

// ---------------- f32x2 helpers ----------------
__device__ __forceinline__ void ffma2(unsigned long long& acc,
                                      unsigned long long a, unsigned long long b) {
    asm("fma.rn.f32x2 %0, %1, %2, %0;" : "+l"(acc) : "l"(a), "l"(b));
}
__device__ __forceinline__ unsigned long long bcast2(float x) {
    unsigned long long r; unsigned u = __float_as_uint(x);
    asm("mov.b64 %0, {%1, %1};" : "=l"(r) : "r"(u));
    return r;
}
__device__ __forceinline__ float2 unpack2(unsigned long long v) {
    unsigned lo, hi;
    asm("mov.b64 {%0, %1}, %2;" : "=r"(lo), "=r"(hi) : "l"(v));
    return make_float2(__uint_as_float(lo), __uint_as_float(hi));
}

// ---------------- tf32 helpers ----------------
__device__ __forceinline__ unsigned f2tf(float x) {
    unsigned r; asm("cvt.rna.tf32.f32 %0, %1;" : "=r"(r) : "f"(x)); return r;
}
__device__ __forceinline__ void split4(const float4& v, uint4& hi, uint4& lo) {
    hi.x = f2tf(v.x); lo.x = f2tf(v.x - __uint_as_float(hi.x));
    hi.y = f2tf(v.y); lo.y = f2tf(v.y - __uint_as_float(hi.y));
    hi.z = f2tf(v.z); lo.z = f2tf(v.z - __uint_as_float(hi.z));
    hi.w = f2tf(v.w); lo.w = f2tf(v.w - __uint_as_float(hi.w));
}
__device__ __forceinline__ void mma_tf32(float c[4], const unsigned a[4],
                                         unsigned b0, unsigned b1) {
    asm volatile(
        "mma.sync.aligned.m16n8k8.row.col.f32.tf32.tf32.f32 "
        "{%0,%1,%2,%3}, {%4,%5,%6,%7}, {%8,%9}, {%0,%1,%2,%3};"
        : "+f"(c[0]), "+f"(c[1]), "+f"(c[2]), "+f"(c[3])
        : "r"(a[0]), "r"(a[1]), "r"(a[2]), "r"(a[3]), "r"(b0), "r"(b1));
}

// ---------------- GEMM: unchanged from round 5 ----------------
extern "C" __global__ void __launch_bounds__(256, 2)
xproj_gemm(const float* __restrict__ x,
           const float* __restrict__ Wi_f, const float* __restrict__ bi_f,
           const float* __restrict__ bh_f,
           const float* __restrict__ Wi_b, const float* __restrict__ bi_b,
           const float* __restrict__ bh_b) {
    const int d = blockIdx.z;
    const float* __restrict__ Wp = d ? Wi_b : Wi_f;
    const float* __restrict__ b1p = d ? bi_b : bi_f;
    const float* __restrict__ b2p = d ? bh_b : bh_f;
    float* __restrict__ xp = g_xp[d];

    extern __shared__ unsigned smg[];
    unsigned* Ah = smg;
    unsigned* Al = Ah + BM * 36;
    unsigned* Bh = Al + BM * 36;
    unsigned* Bl = Bh + BK * 72;

    const int tid = threadIdx.x;
    const int wid = tid >> 5, lane = tid & 31;
    const int wm = wid >> 1, wn = wid & 1;
    const int gid = lane >> 2, tig = lane & 3;
    const int m0 = blockIdx.y * BM, n0 = blockIdx.x * BN;
    const int bb = m0 >> 9, s0 = m0 & 511;
    const float* Ag = x + ((size_t)bb * S_ + s0) * I_;

    const int ar = tid >> 3, ak = (tid & 7) * 4;
    const int br = tid >> 4, bn = (tid & 15) * 4;

    float acc[2][4][4];
#pragma unroll
    for (int mi = 0; mi < 2; ++mi)
#pragma unroll
        for (int ni = 0; ni < 4; ++ni)
#pragma unroll
            for (int j = 0; j < 4; ++j) acc[mi][ni][j] = 0.f;

    for (int t = 0; t < NTILE; ++t) {
        const int kt = t * BK;
        float4 pa[4], pb[2];
#pragma unroll
        for (int j = 0; j < 4; ++j)
            pa[j] = *(const float4*)(Ag + (size_t)(ar + 32 * j) * I_ + kt + ak);
#pragma unroll
        for (int j = 0; j < 2; ++j)
            pb[j] = *(const float4*)(Wp + (size_t)(kt + br + 16 * j) * G4 + n0 + bn);
        __syncthreads();
#pragma unroll
        for (int j = 0; j < 4; ++j) {
            uint4 hi, lo; split4(pa[j], hi, lo);
            *(uint4*)&Ah[(ar + 32 * j) * 36 + ak] = hi;
            *(uint4*)&Al[(ar + 32 * j) * 36 + ak] = lo;
        }
#pragma unroll
        for (int j = 0; j < 2; ++j) {
            uint4 hi, lo; split4(pb[j], hi, lo);
            *(uint4*)&Bh[(br + 16 * j) * 72 + bn] = hi;
            *(uint4*)&Bl[(br + 16 * j) * 72 + bn] = lo;
        }
        __syncthreads();

#pragma unroll
        for (int ks = 0; ks < 4; ++ks) {
            const int k0 = ks * 8;
            unsigned ahr[2][4], alr[2][4];
#pragma unroll
            for (int mi = 0; mi < 2; ++mi) {
                const int base = wm * 32 + mi * 16;
                const int i0 = (base + gid) * 36 + k0 + tig;
                const int i1 = (base + gid + 8) * 36 + k0 + tig;
                ahr[mi][0] = Ah[i0];     alr[mi][0] = Al[i0];
                ahr[mi][1] = Ah[i1];     alr[mi][1] = Al[i1];
                ahr[mi][2] = Ah[i0 + 4]; alr[mi][2] = Al[i0 + 4];
                ahr[mi][3] = Ah[i1 + 4]; alr[mi][3] = Al[i1 + 4];
            }
            unsigned bhr[4][2], blr[4][2];
#pragma unroll
            for (int ni = 0; ni < 4; ++ni) {
                const int i0 = (k0 + tig) * 72 + wn * 32 + ni * 8 + gid;
                bhr[ni][0] = Bh[i0];          blr[ni][0] = Bl[i0];
                bhr[ni][1] = Bh[i0 + 4 * 72]; blr[ni][1] = Bl[i0 + 4 * 72];
            }
#pragma unroll
            for (int mi = 0; mi < 2; ++mi)
#pragma unroll
                for (int ni = 0; ni < 4; ++ni) {
                    mma_tf32(acc[mi][ni], ahr[mi], bhr[ni][0], bhr[ni][1]);
                    mma_tf32(acc[mi][ni], ahr[mi], blr[ni][0], blr[ni][1]);
                    mma_tf32(acc[mi][ni], alr[mi], bhr[ni][0], bhr[ni][1]);
                }
        }
    }

#pragma unroll
    for (int mi = 0; mi < 2; ++mi) {
        const int sA = s0 + wm * 32 + mi * 16 + gid;
#pragma unroll
        for (int ni = 0; ni < 4; ++ni) {
            const int gn = n0 + wn * 32 + ni * 8 + 2 * tig;
            const float c0 = b1p[gn] + b2p[gn];
            const float c1 = b1p[gn + 1] + b2p[gn + 1];
            *(float2*)&xp[((size_t)sA * B_ + bb) * G4 + gn] =
                make_float2(acc[mi][ni][0] + c0, acc[mi][ni][1] + c1);
            *(float2*)&xp[((size_t)(sA + 8) * B_ + bb) * G4 + gn] =
                make_float2(acc[mi][ni][2] + c0, acc[mi][ni][3] + c1);
        }
    }
}

__device__ __forceinline__ float sigmf(float x) { return 1.0f / (1.0f + expf(-x)); }

__device__ __forceinline__ unsigned ld_acq(const unsigned* p) {
    unsigned v;
    asm volatile("ld.global.acquire.gpu.u32 %0, [%1];" : "=r"(v) : "l"(p));
    return v;
}
__device__ __forceinline__ void st_rel(unsigned* p, unsigned v) {
    asm volatile("st.global.release.gpu.u32 [%0], %1;" :: "l"(p), "r"(v));
}

// Per-direction barrier over 64 blocks.
__device__ __forceinline__ void dir_bar(int d, unsigned tgt) {
    __syncthreads();
    if (threadIdx.x == 0) {
        __threadfence();
        unsigned arr = atomicAdd(&g_cnt[d], 1u) + 1u;
        if (arr == 64u * tgt) st_rel(&g_gen2[d], tgt);
        else while (ld_acq(&g_gen2[d]) < tgt) __nanosleep(32);
    }
    __syncthreads();
}

// 128 persistent blocks, 512 threads. dir = blk>>6; block owns 8 hidden units.
// K-split x2 across thread halves + smem reduction; f32x2 packed FMA.
extern "C" __global__ void __launch_bounds__(512, 1)
lstm_recur(const float* __restrict__ sent, float* __restrict__ out,
           const float* __restrict__ Wh_f, const float* __restrict__ Wh_b) {
    const int blk = blockIdx.x, d = blk >> 6, u0 = (blk & 63) * 8;
    const float* __restrict__ Wh = d ? Wh_b : Wh_f;
    const float* __restrict__ xp = g_xp[d];

    extern __shared__ float sm[];
    float* hs = sm;                             // [64][516]
    float* Ws = sm + 64 * HS_LD;                // [512][32]
    unsigned long long* ps =
        (unsigned long long*)(Ws + 512 * 32);   // [256][2][4] f32x2 partials
    float* gb = (float*)(ps + 256 * 2 * 4);     // [64][32]
    float* cs = gb + 64 * 32;                   // [64][8]

    const int tid = threadIdx.x;
    for (int i = tid; i < 512 * 32; i += 512) {
        const int k = i >> 5, c = i & 31;
        Ws[i] = Wh[(size_t)k * G4 + (c >> 3) * H_ + u0 + (c & 7)];
    }
    for (int i = tid; i < 512; i += 512) {
        cs[i] = 0.f;
        g_h[d][0][(i >> 3) * H_ + u0 + (i & 7)] = 0.f;
    }
    unsigned barno = 1;
    dir_bar(d, barno);

    const int kh = tid >> 8;                    // K half 0/1
    const int r = tid & 255;
    const int w = r >> 5, l = r & 31;
    const int cg = (l & 3) + ((w & 1) << 2);    // 8 col groups x 4 cols
    const int bg = (l >> 2) + ((w >> 1) << 3);  // 32 batch pairs
    const int b0r = bg * 2, b1r = b0r + 1, cc0 = cg * 4;
    const int gcol0 = (cc0 >> 3) * H_ + u0 + (cc0 & 7);
    const int ub = tid >> 3, uu = tid & 7;      // cell update: 1 (b,u)/thread
    const float* __restrict__ sent_b = sent + (size_t)ub * S_;

    for (int t = 0; t < S_; ++t) {
        const int tt = d ? (S_ - 1 - t) : t;
        const float* __restrict__ hr = g_h[d][t & 1];
        float* __restrict__ hw = g_h[d][1 - (t & 1)];

        for (int i = tid; i < 64 * 128; i += 512) {
            const int b = i >> 7, q = (i & 127) << 2;
            *(float4*)&hs[b * HS_LD + q] = *(const float4*)&hr[b * H_ + q];
        }
        float4 x0, x1;
        if (kh == 0) {  // reduce threads prefetch xp
            x0 = *(const float4*)&xp[((size_t)tt * B_ + b0r) * G4 + gcol0];
            x1 = *(const float4*)&xp[((size_t)tt * B_ + b1r) * G4 + gcol0];
        }
        __syncthreads();

        unsigned long long acc0 = 0ull, acc1 = 0ull, acc2 = 0ull, acc3 = 0ull;
        const float* hp0 = hs + b0r * HS_LD + kh * 256;
        const float* hp1 = hs + b1r * HS_LD + kh * 256;
        const float* wp = Ws + cc0 + kh * 256 * 32;
#pragma unroll 4
        for (int k = 0; k < 256; k += 4) {
            const float4 h0 = *(const float4*)(hp0 + k);
            const float4 h1 = *(const float4*)(hp1 + k);
            const ulonglong2 w0 = *(const ulonglong2*)(wp + (k + 0) * 32);
            const ulonglong2 w1 = *(const ulonglong2*)(wp + (k + 1) * 32);
            const ulonglong2 w2 = *(const ulonglong2*)(wp + (k + 2) * 32);
            const ulonglong2 w3 = *(const ulonglong2*)(wp + (k + 3) * 32);
#define KS(hc0, hc1, wv) { \
            const unsigned long long hh0 = bcast2(hc0), hh1 = bcast2(hc1); \
            ffma2(acc0, hh0, (wv).x); ffma2(acc1, hh0, (wv).y); \
            ffma2(acc2, hh1, (wv).x); ffma2(acc3, hh1, (wv).y); }
            KS(h0.x, h1.x, w0) KS(h0.y, h1.y, w1) KS(h0.z, h1.z, w2) KS(h0.w, h1.w, w3)
#undef KS
        }
        {
            unsigned long long* pp = ps + (r * 2 + kh) * 4;
            pp[0] = acc0; pp[1] = acc1; pp[2] = acc2; pp[3] = acc3;
        }
        __syncthreads();

        if (kh == 0) {
            const unsigned long long* pa = ps + r * 8;
            const float2 a0 = unpack2(pa[0]), a1 = unpack2(pa[1]);
            const float2 a2 = unpack2(pa[2]), a3 = unpack2(pa[3]);
            const float2 c0 = unpack2(pa[4]), c1 = unpack2(pa[5]);
            const float2 c2 = unpack2(pa[6]), c3 = unpack2(pa[7]);
            gb[b0r*32+cc0+0] = a0.x + c0.x + x0.x;
            gb[b0r*32+cc0+1] = a0.y + c0.y + x0.y;
            gb[b0r*32+cc0+2] = a1.x + c1.x + x0.z;
            gb[b0r*32+cc0+3] = a1.y + c1.y + x0.w;
            gb[b1r*32+cc0+0] = a2.x + c2.x + x1.x;
            gb[b1r*32+cc0+1] = a2.y + c2.y + x1.y;
            gb[b1r*32+cc0+2] = a3.x + c3.x + x1.z;
            gb[b1r*32+cc0+3] = a3.y + c3.y + x1.w;
        }
        __syncthreads();

        {
            const float xi = gb[ub*32+uu],    xf = gb[ub*32+8+uu];
            const float xg = gb[ub*32+16+uu], xo = gb[ub*32+24+uu];
            const float st = sent_b[tt];
            const float iv = sigmf(xi) * st;
            const float fv = sigmf(xf) * (1.0f + st);
            const float cv = fv * cs[tid] + iv * tanhf(xg);
            cs[tid] = cv;
            const float hv = sigmf(xo) * tanhf(cv);
            hw[ub * H_ + u0 + uu] = hv;
            out[((size_t)ub * S_ + tt) * (2 * H_) + d * H_ + u0 + uu] = hv;
        }
        ++barno;
        dir_bar(d, barno);
    }
}

extern "C" void kernel_launch(void* const* d_in, const int* in_sizes, int n_in,
                              void* d_out, int out_size) {
    const float* x    = (const float*)d_in[0];
    const float* sent = (const float*)d_in[1];
    const float* Wi_f = (const float*)d_in[2];
    const float* bi_f = (const float*)d_in[3];
    const float* Wh_f = (const float*)d_in[4];
    const float* bh_f = (const float*)d_in[5];
    const float* Wi_b = (const float*)d_in[6];
    const float* bi_b = (const float*)d_in[7];
    const float* Wh_b = (const float*)d_in[8];
    const float* bh_b = (const float*)d_in[9];
    float* out = (float*)d_out;

    static bool attr_done = false;
    if (!attr_done) {
        cudaFuncSetAttribute(lstm_recur, cudaFuncAttributeMaxDynamicSharedMemorySize,
                             REC_SMEM);
        cudaFuncSetAttribute(xproj_gemm, cudaFuncAttributeMaxDynamicSharedMemorySize,
                             GEMM_SMEM);
        attr_done = true;
    }

    dim3 ggrid(G4 / BN, (B_ * S_) / BM, 2);
    xproj_gemm<<<ggrid, 256, GEMM_SMEM>>>(x, Wi_f, bi_f, bh_f, Wi_b, bi_b, bh_b);
    init_sync_kernel<<<1, 1>>>();
    lstm_recur<<<128, 512, REC_SMEM>>>(sent, out, Wh_f, Wh_b);
}

// round 7
// speedup vs baseline: 2.1548x; 2.1548x over previous
#include <cuda_runtime.h>
#include <math.h>

namespace {
constexpr int B_ = 64, S_ = 512, I_ = 768, H_ = 512, G4 = 2048;
constexpr int BM = 128, BN = 64, BK = 32, NTILE = I_ / BK;
constexpr int GBP_LD = 34;
constexpr int REC_SMEM = 64 * 4 * 32 * 16 /*Bfrag*/ + 2 * 64 * GBP_LD * 4 /*gbp*/
                       + 512 * 4 /*cs*/;
constexpr int GEMM_SMEM = (2 * BM * 36 + 2 * BK * 72) * 4;
}

__device__ float g_xp[2][(size_t)S_ * B_ * G4];
// h in MMA-fragment order, tf32 hi/lo pre-split: [dir][buf][slot*2 + (0=hi,1=lo)]
__device__ uint4 g_A[2][2][64 * 4 * 32 * 2];
__device__ unsigned g_cnt[2], g_gen2[2];

__global__ void init_sync_kernel() {
    g_cnt[0] = g_cnt[1] = 0u;
    g_gen2[0] = g_gen2[1] = 0u;
}

// ---------------- tf32 helpers ----------------
__device__ __forceinline__ unsigned f2tf(float x) {
    unsigned r; asm("cvt.rna.tf32.f32 %0, %1;" : "=r"(r) : "f"(x)); return r;
}
__device__ __forceinline__ void split4(const float4& v, uint4& hi, uint4& lo) {
    hi.x = f2tf(v.x); lo.x = f2tf(v.x - __uint_as_float(hi.x));
    hi.y = f2tf(v.y); lo.y = f2tf(v.y - __uint_as_float(hi.y));
    hi.z = f2tf(v.z); lo.z = f2tf(v.z - __uint_as_float(hi.z));
    hi.w = f2tf(v.w); lo.w = f2tf(v.w - __uint_as_float(hi.w));
}
__device__ __forceinline__ void mma_tf32(float c[4], const unsigned a[4],
                                         unsigned b0, unsigned b1) {
    asm volatile(
        "mma.sync.aligned.m16n8k8.row.col.f32.tf32.tf32.f32 "
        "{%0,%1,%2,%3}, {%4,%5,%6,%7}, {%8,%9}, {%0,%1,%2,%3};"
        : "+f"(c[0]), "+f"(c[1]), "+f"(c[2]), "+f"(c[3])
        : "r"(a[0]), "r"(a[1]), "r"(a[2]), "r"(a[3]), "r"(b0), "r"(b1));
}
__device__ __forceinline__ void mma_tf32u(float c[4], const uint4& a,
                                          unsigned b0, unsigned b1) {
    asm volatile(
        "mma.sync.aligned.m16n8k8.row.col.f32.tf32.tf32.f32 "
        "{%0,%1,%2,%3}, {%4,%5,%6,%7}, {%8,%9}, {%0,%1,%2,%3};"
        : "+f"(c[0]), "+f"(c[1]), "+f"(c[2]), "+f"(c[3])
        : "r"(a.x), "r"(a.y), "r"(a.z), "r"(a.w), "r"(b0), "r"(b1));
}

// ---------------- GEMM: unchanged (round 5, proven) ----------------
extern "C" __global__ void __launch_bounds__(256, 2)
xproj_gemm(const float* __restrict__ x,
           const float* __restrict__ Wi_f, const float* __restrict__ bi_f,
           const float* __restrict__ bh_f,
           const float* __restrict__ Wi_b, const float* __restrict__ bi_b,
           const float* __restrict__ bh_b) {
    const int d = blockIdx.z;
    const float* __restrict__ Wp = d ? Wi_b : Wi_f;
    const float* __restrict__ b1p = d ? bi_b : bi_f;
    const float* __restrict__ b2p = d ? bh_b : bh_f;
    float* __restrict__ xp = g_xp[d];

    extern __shared__ unsigned smg[];
    unsigned* Ah = smg;
    unsigned* Al = Ah + BM * 36;
    unsigned* Bh = Al + BM * 36;
    unsigned* Bl = Bh + BK * 72;

    const int tid = threadIdx.x;
    const int wid = tid >> 5, lane = tid & 31;
    const int wm = wid >> 1, wn = wid & 1;
    const int gid = lane >> 2, tig = lane & 3;
    const int m0 = blockIdx.y * BM, n0 = blockIdx.x * BN;
    const int bb = m0 >> 9, s0 = m0 & 511;
    const float* Ag = x + ((size_t)bb * S_ + s0) * I_;

    const int ar = tid >> 3, ak = (tid & 7) * 4;
    const int br = tid >> 4, bn = (tid & 15) * 4;

    float acc[2][4][4];
#pragma unroll
    for (int mi = 0; mi < 2; ++mi)
#pragma unroll
        for (int ni = 0; ni < 4; ++ni)
#pragma unroll
            for (int j = 0; j < 4; ++j) acc[mi][ni][j] = 0.f;

    for (int t = 0; t < NTILE; ++t) {
        const int kt = t * BK;
        float4 pa[4], pb[2];
#pragma unroll
        for (int j = 0; j < 4; ++j)
            pa[j] = *(const float4*)(Ag + (size_t)(ar + 32 * j) * I_ + kt + ak);
#pragma unroll
        for (int j = 0; j < 2; ++j)
            pb[j] = *(const float4*)(Wp + (size_t)(kt + br + 16 * j) * G4 + n0 + bn);
        __syncthreads();
#pragma unroll
        for (int j = 0; j < 4; ++j) {
            uint4 hi, lo; split4(pa[j], hi, lo);
            *(uint4*)&Ah[(ar + 32 * j) * 36 + ak] = hi;
            *(uint4*)&Al[(ar + 32 * j) * 36 + ak] = lo;
        }
#pragma unroll
        for (int j = 0; j < 2; ++j) {
            uint4 hi, lo; split4(pb[j], hi, lo);
            *(uint4*)&Bh[(br + 16 * j) * 72 + bn] = hi;
            *(uint4*)&Bl[(br + 16 * j) * 72 + bn] = lo;
        }
        __syncthreads();

#pragma unroll
        for (int ks = 0; ks < 4; ++ks) {
            const int k0 = ks * 8;
            unsigned ahr[2][4], alr[2][4];
#pragma unroll
            for (int mi = 0; mi < 2; ++mi) {
                const int base = wm * 32 + mi * 16;
                const int i0 = (base + gid) * 36 + k0 + tig;
                const int i1 = (base + gid + 8) * 36 + k0 + tig;
                ahr[mi][0] = Ah[i0];     alr[mi][0] = Al[i0];
                ahr[mi][1] = Ah[i1];     alr[mi][1] = Al[i1];
                ahr[mi][2] = Ah[i0 + 4]; alr[mi][2] = Al[i0 + 4];
                ahr[mi][3] = Ah[i1 + 4]; alr[mi][3] = Al[i1 + 4];
            }
            unsigned bhr[4][2], blr[4][2];
#pragma unroll
            for (int ni = 0; ni < 4; ++ni) {
                const int i0 = (k0 + tig) * 72 + wn * 32 + ni * 8 + gid;
                bhr[ni][0] = Bh[i0];          blr[ni][0] = Bl[i0];
                bhr[ni][1] = Bh[i0 + 4 * 72]; blr[ni][1] = Bl[i0 + 4 * 72];
            }
#pragma unroll
            for (int mi = 0; mi < 2; ++mi)
#pragma unroll
                for (int ni = 0; ni < 4; ++ni) {
                    mma_tf32(acc[mi][ni], ahr[mi], bhr[ni][0], bhr[ni][1]);
                    mma_tf32(acc[mi][ni], ahr[mi], blr[ni][0], blr[ni][1]);
                    mma_tf32(acc[mi][ni], alr[mi], bhr[ni][0], bhr[ni][1]);
                }
        }
    }

#pragma unroll
    for (int mi = 0; mi < 2; ++mi) {
        const int sA = s0 + wm * 32 + mi * 16 + gid;
#pragma unroll
        for (int ni = 0; ni < 4; ++ni) {
            const int gn = n0 + wn * 32 + ni * 8 + 2 * tig;
            const float c0 = b1p[gn] + b2p[gn];
            const float c1 = b1p[gn + 1] + b2p[gn + 1];
            *(float2*)&xp[((size_t)sA * B_ + bb) * G4 + gn] =
                make_float2(acc[mi][ni][0] + c0, acc[mi][ni][1] + c1);
            *(float2*)&xp[((size_t)(sA + 8) * B_ + bb) * G4 + gn] =
                make_float2(acc[mi][ni][2] + c0, acc[mi][ni][3] + c1);
        }
    }
}

__device__ __forceinline__ float sigmf(float x) { return 1.0f / (1.0f + expf(-x)); }

__device__ __forceinline__ unsigned ld_acq(const unsigned* p) {
    unsigned v;
    asm volatile("ld.global.acquire.gpu.u32 %0, [%1];" : "=r"(v) : "l"(p));
    return v;
}
__device__ __forceinline__ void st_rel(unsigned* p, unsigned v) {
    asm volatile("st.global.release.gpu.u32 [%0], %1;" :: "l"(p), "r"(v));
}
__device__ __forceinline__ void dir_bar(int d, unsigned tgt) {
    __syncthreads();
    if (threadIdx.x == 0) {
        __threadfence();
        unsigned arr = atomicAdd(&g_cnt[d], 1u) + 1u;
        if (arr == 64u * tgt) st_rel(&g_gen2[d], tgt);
        else while (ld_acq(&g_gen2[d]) < tgt) __nanosleep(32);
    }
    __syncthreads();
}

// 128 persistent blocks, 256 threads. dir = blk>>6; block owns 8 hidden units
// (32 gate cols). Recurrence GEMM on mma.sync tf32x3:
//   per block/step: C[64 x 32] = h[64 x 512] @ Whslice[512 x 32]
// warps: mt = wid&3 (16 batch rows), kh = wid>>2 (K half). A frags from global
// (producer pre-split, fragment order); B frags packed in smem at init.
extern "C" __global__ void __launch_bounds__(256, 1)
lstm_recur(const float* __restrict__ sent, float* __restrict__ out,
           const float* __restrict__ Wh_f, const float* __restrict__ Wh_b) {
    const int blk = blockIdx.x, d = blk >> 6, grp = blk & 63, u0 = grp * 8;
    const float* __restrict__ Wh = d ? Wh_b : Wh_f;
    const float* __restrict__ xp = g_xp[d];

    extern __shared__ unsigned smr[];
    uint4* Bs = (uint4*)smr;                      // [64 ks][4 nt][32 lane] {b0h,b1h,b0l,b1l}
    float* gbp = (float*)(Bs + 64 * 4 * 32);      // [2][64][GBP_LD]
    float* cs = gbp + 2 * 64 * GBP_LD;            // [512]

    const int tid = threadIdx.x;
    const int wid = tid >> 5, lane = tid & 31;
    const int gid = lane >> 2, tig = lane & 3;
    const int mt = wid & 3, kh = wid >> 2;

    // ---- init: pack Wh slice into fragment order (once) ----
    for (int i = tid; i < 64 * 4 * 32; i += 256) {
        const int ks = i >> 7, nt = (i >> 5) & 3, ln = i & 31;
        const int g2 = ln >> 2, t2 = ln & 3;
        const int col = nt * H_ + u0 + g2;
        const float w0 = Wh[(size_t)(ks * 8 + t2) * G4 + col];
        const float w1 = Wh[(size_t)(ks * 8 + t2 + 4) * G4 + col];
        uint4 v;
        v.x = f2tf(w0); v.z = f2tf(w0 - __uint_as_float(v.x));
        v.y = f2tf(w1); v.w = f2tf(w1 - __uint_as_float(v.y));
        Bs[i] = v;
    }
    for (int i = tid; i < 512; i += 256) cs[i] = 0.f;
    {   // zero buf0 h-frags: this block's 1/64 slice of the dir's 16384 uint4
        const uint4 z = make_uint4(0u, 0u, 0u, 0u);
        g_A[d][0][grp * 256 + tid] = z;
    }
    unsigned barno = 1;
    dir_bar(d, barno);

    for (int t = 0; t < S_; ++t) {
        const int tt = d ? (S_ - 1 - t) : t;
        const uint4* __restrict__ Ab = g_A[d][t & 1];
        const int wbuf = 1 - (t & 1);

        float acc[4][4];
#pragma unroll
        for (int nt = 0; nt < 4; ++nt)
#pragma unroll
            for (int j = 0; j < 4; ++j) acc[nt][j] = 0.f;

        // software-pipelined A frags (global, L1-bypass)
        int slot = ((kh * 32) * 4 + mt) * 32 + lane;
        uint4 nah = __ldcg(&Ab[slot * 2]);
        uint4 nal = __ldcg(&Ab[slot * 2 + 1]);
#pragma unroll 4
        for (int ksl = 0; ksl < 32; ++ksl) {
            const uint4 ah = nah, al = nal;
            if (ksl < 31) {
                const int ns = (((kh * 32 + ksl + 1) * 4 + mt) * 32 + lane) * 2;
                nah = __ldcg(&Ab[ns]);
                nal = __ldcg(&Ab[ns + 1]);
            }
            const int ks = kh * 32 + ksl;
            const uint4* bp = &Bs[(ks * 4) * 32 + lane];
#pragma unroll
            for (int nt = 0; nt < 4; ++nt) {
                const uint4 bb = bp[nt * 32];
                mma_tf32u(acc[nt], ah, bb.x, bb.y);   // hi*hi
                mma_tf32u(acc[nt], ah, bb.z, bb.w);   // hi*lo
                mma_tf32u(acc[nt], al, bb.x, bb.y);   // lo*hi
            }
        }

        // partials to smem
        {
            float* gp = gbp + kh * (64 * GBP_LD);
            const int r0 = mt * 16 + gid;
#pragma unroll
            for (int nt = 0; nt < 4; ++nt) {
                *(float2*)&gp[r0 * GBP_LD + nt * 8 + 2 * tig] =
                    make_float2(acc[nt][0], acc[nt][1]);
                *(float2*)&gp[(r0 + 8) * GBP_LD + nt * 8 + 2 * tig] =
                    make_float2(acc[nt][2], acc[nt][3]);
            }
        }
        __syncthreads();

        // cell update: 2 (b,u) per thread
#pragma unroll
        for (int pp = 0; pp < 2; ++pp) {
            const int p = tid * 2 + pp, b = p >> 3, u = p & 7;
            const float* g0 = gbp + b * GBP_LD + u;
            const float* g1 = g0 + 64 * GBP_LD;
            const float* xb = xp + ((size_t)tt * B_ + b) * G4 + u0 + u;
            const float xi = g0[0]  + g1[0]  + xb[0];
            const float xf = g0[8]  + g1[8]  + xb[H_];
            const float xg = g0[16] + g1[16] + xb[2 * H_];
            const float xo = g0[24] + g1[24] + xb[3 * H_];
            const float st = sent[(size_t)b * S_ + tt];
            const float iv = sigmf(xi) * st;
            const float fv = sigmf(xf) * (1.0f + st);
            const float cv = fv * cs[p] + iv * tanhf(xg);
            cs[p] = cv;
            const float hv = sigmf(xo) * tanhf(cv);
            out[((size_t)b * S_ + tt) * (2 * H_) + d * H_ + u0 + u] = hv;
            // write h split into fragment order for next step
            const int hidx = u0 + u;
            const int ks = hidx >> 3, t2 = hidx & 3, half = (hidx >> 2) & 1;
            const int g2 = b & 7, rh = (b >> 3) & 1, m2 = b >> 4;
            const int sl = (ks * 4 + m2) * 32 + g2 * 4 + t2;
            unsigned* bas = (unsigned*)&g_A[d][wbuf][sl * 2];
            const unsigned hb = f2tf(hv);
            const unsigned lb = f2tf(hv - __uint_as_float(hb));
            bas[half * 2 + rh] = hb;
            bas[4 + half * 2 + rh] = lb;
        }
        ++barno;
        dir_bar(d, barno);
    }
}

extern "C" void kernel_launch(void* const* d_in, const int* in_sizes, int n_in,
                              void* d_out, int out_size) {
    const float* x    = (const float*)d_in[0];
    const float* sent = (const float*)d_in[1];
    const float* Wi_f = (const float*)d_in[2];
    const float* bi_f = (const float*)d_in[3];
    const float* Wh_f = (const float*)d_in[4];
    const float* bh_f = (const float*)d_in[5];
    const float* Wi_b = (const float*)d_in[6];
    const float* bi_b = (const float*)d_in[7];
    const float* Wh_b = (const float*)d_in[8];
    const float* bh_b = (const float*)d_in[9];
    float* out = (float*)d_out;

    static bool attr_done = false;
    if (!attr_done) {
        cudaFuncSetAttribute(lstm_recur, cudaFuncAttributeMaxDynamicSharedMemorySize,
                             REC_SMEM);
        cudaFuncSetAttribute(xproj_gemm, cudaFuncAttributeMaxDynamicSharedMemorySize,
                             GEMM_SMEM);
        attr_done = true;
    }

    dim3 ggrid(G4 / BN, (B_ * S_) / BM, 2);
    xproj_gemm<<<ggrid, 256, GEMM_SMEM>>>(x, Wi_f, bi_f, bh_f, Wi_b, bi_b, bh_b);
    init_sync_kernel<<<1, 1>>>();
    lstm_recur<<<128, 256, REC_SMEM>>>(sent, out, Wh_f, Wh_b);
}

// round 11
// speedup vs baseline: 2.9956x; 1.3902x over previous
#include <cuda_runtime.h>
#include <cuda_fp16.h>
#include <math.h>

namespace {
constexpr int B_ = 64, S_ = 512, I_ = 768, H_ = 512, G4 = 2048;
constexpr int BM = 128, BN = 64, BK = 32, NTILE = I_ / BK;
constexpr int GBP_LD = 34;
constexpr int REC_SMEM = 32 * 4 * 32 * 16 /*B frags*/ + 2 * 64 * GBP_LD * 4 /*gbp*/;
constexpr int GEMM_SMEM = (2 * 128 * 20 + 2 * 16 * 72) * 4;
constexpr float SC = 256.0f;               // operand pre-scale (2^8)
constexpr float DSC = 1.0f / 65536.0f;     // accumulator descale (2^-16)
}

__device__ float g_xp[2][(size_t)S_ * B_ * G4];
// h in m16n8k16 A-fragment order, fp16 hi/lo (scaled by 2^8): [dir][buf]
__device__ uint4 g_A[2][2][8192];
__device__ unsigned g_cnt[2], g_gen2[2];

__global__ void init_sync_kernel() {
    g_cnt[0] = g_cnt[1] = 0u;
    g_gen2[0] = g_gen2[1] = 0u;
}

// split pre-scaled float pair into packed fp16x2 hi + residual lo
__device__ __forceinline__ void hsplit2(float x0, float x1, unsigned& hi, unsigned& lo) {
    __half2 h = __floats2half2_rn(x0, x1);
    const float f0 = __low2float(h), f1 = __high2float(h);
    __half2 l = __floats2half2_rn(x0 - f0, x1 - f1);
    hi = *reinterpret_cast<unsigned*>(&h);
    lo = *reinterpret_cast<unsigned*>(&l);
}

__device__ __forceinline__ void mma_f16(float c[4], const unsigned a[4],
                                        unsigned b0, unsigned b1) {
    asm volatile(
        "mma.sync.aligned.m16n8k16.row.col.f32.f16.f16.f32 "
        "{%0,%1,%2,%3}, {%4,%5,%6,%7}, {%8,%9}, {%0,%1,%2,%3};"
        : "+f"(c[0]), "+f"(c[1]), "+f"(c[2]), "+f"(c[3])
        : "r"(a[0]), "r"(a[1]), "r"(a[2]), "r"(a[3]), "r"(b0), "r"(b1));
}
__device__ __forceinline__ void mma_f16u(float c[4], const uint4& a,
                                         unsigned b0, unsigned b1) {
    asm volatile(
        "mma.sync.aligned.m16n8k16.row.col.f32.f16.f16.f32 "
        "{%0,%1,%2,%3}, {%4,%5,%6,%7}, {%8,%9}, {%0,%1,%2,%3};"
        : "+f"(c[0]), "+f"(c[1]), "+f"(c[2]), "+f"(c[3])
        : "r"(a.x), "r"(a.y), "r"(a.z), "r"(a.w), "r"(b0), "r"(b1));
}

// C[(b,s), n] = x @ Wi + bi + bh -> g_xp[d][s][b][n], fp16x2-split (scaled)
extern "C" __global__ void __launch_bounds__(256, 2)
xproj_gemm(const float* __restrict__ x,
           const float* __restrict__ Wi_f, const float* __restrict__ bi_f,
           const float* __restrict__ bh_f,
           const float* __restrict__ Wi_b, const float* __restrict__ bi_b,
           const float* __restrict__ bh_b) {
    const int d = blockIdx.z;
    const float* __restrict__ Wp = d ? Wi_b : Wi_f;
    const float* __restrict__ b1p = d ? bi_b : bi_f;
    const float* __restrict__ b2p = d ? bh_b : bh_f;
    float* __restrict__ xp = g_xp[d];

    extern __shared__ unsigned smg[];
    unsigned* Ah = smg;                 // [128 rows][20 kwords] fp16x2
    unsigned* Al = Ah + 128 * 20;
    unsigned* Bh = Al + 128 * 20;       // [16 kwords][72 n]
    unsigned* Bl = Bh + 16 * 72;

    const int tid = threadIdx.x;
    const int wid = tid >> 5, lane = tid & 31;
    const int wm = wid >> 1, wn = wid & 1;
    const int gid = lane >> 2, tig = lane & 3;
    const int m0 = blockIdx.y * BM, n0 = blockIdx.x * BN;
    const int bb = m0 >> 9, s0 = m0 & 511;
    const float* Ag = x + ((size_t)bb * S_ + s0) * I_;

    const int ar = tid >> 3, ak = (tid & 7) * 4, aw = (tid & 7) * 2;
    const int bkw = tid & 15, bn0 = (tid >> 4) * 4;

    float acc[2][4][4];
#pragma unroll
    for (int mi = 0; mi < 2; ++mi)
#pragma unroll
        for (int ni = 0; ni < 4; ++ni)
#pragma unroll
            for (int j = 0; j < 4; ++j) acc[mi][ni][j] = 0.f;

    for (int t = 0; t < NTILE; ++t) {
        const int kt = t * BK;
        float4 pa[4];
#pragma unroll
        for (int j = 0; j < 4; ++j)
            pa[j] = *(const float4*)(Ag + (size_t)(ar + 32 * j) * I_ + kt + ak);
        const float4 p0 = *(const float4*)(Wp + (size_t)(kt + 2 * bkw) * G4 + n0 + bn0);
        const float4 p1 = *(const float4*)(Wp + (size_t)(kt + 2 * bkw + 1) * G4 + n0 + bn0);
        __syncthreads();
#pragma unroll
        for (int j = 0; j < 4; ++j) {
            unsigned h0, l0, h1, l1;
            hsplit2(pa[j].x * SC, pa[j].y * SC, h0, l0);
            hsplit2(pa[j].z * SC, pa[j].w * SC, h1, l1);
            const int row = (ar + 32 * j) * 20 + aw;
            *(uint2*)&Ah[row] = make_uint2(h0, h1);
            *(uint2*)&Al[row] = make_uint2(l0, l1);
        }
        {
            uint4 vh, vl;
            hsplit2(p0.x * SC, p1.x * SC, vh.x, vl.x);
            hsplit2(p0.y * SC, p1.y * SC, vh.y, vl.y);
            hsplit2(p0.z * SC, p1.z * SC, vh.z, vl.z);
            hsplit2(p0.w * SC, p1.w * SC, vh.w, vl.w);
            *(uint4*)&Bh[bkw * 72 + bn0] = vh;
            *(uint4*)&Bl[bkw * 72 + bn0] = vl;
        }
        __syncthreads();

#pragma unroll
        for (int ks = 0; ks < 2; ++ks) {
            const int k0w = ks * 8;
            unsigned ahr[2][4], alr[2][4];
#pragma unroll
            for (int mi = 0; mi < 2; ++mi) {
                const int r0 = (wm * 32 + mi * 16 + gid) * 20 + k0w + tig;
                const int r1 = r0 + 8 * 20;
                ahr[mi][0] = Ah[r0]; ahr[mi][1] = Ah[r1];
                ahr[mi][2] = Ah[r0 + 4]; ahr[mi][3] = Ah[r1 + 4];
                alr[mi][0] = Al[r0]; alr[mi][1] = Al[r1];
                alr[mi][2] = Al[r0 + 4]; alr[mi][3] = Al[r1 + 4];
            }
            unsigned bhr[4][2], blr[4][2];
#pragma unroll
            for (int ni = 0; ni < 4; ++ni) {
                const int i0 = (k0w + tig) * 72 + wn * 32 + ni * 8 + gid;
                const int i1 = i0 + 4 * 72;
                bhr[ni][0] = Bh[i0]; bhr[ni][1] = Bh[i1];
                blr[ni][0] = Bl[i0]; blr[ni][1] = Bl[i1];
            }
#pragma unroll
            for (int mi = 0; mi < 2; ++mi)
#pragma unroll
                for (int ni = 0; ni < 4; ++ni) {
                    mma_f16(acc[mi][ni], ahr[mi], bhr[ni][0], bhr[ni][1]);
                    mma_f16(acc[mi][ni], ahr[mi], blr[ni][0], blr[ni][1]);
                    mma_f16(acc[mi][ni], alr[mi], bhr[ni][0], bhr[ni][1]);
                }
        }
    }

#pragma unroll
    for (int mi = 0; mi < 2; ++mi) {
        const int sA = s0 + wm * 32 + mi * 16 + gid;
#pragma unroll
        for (int ni = 0; ni < 4; ++ni) {
            const int gn = n0 + wn * 32 + ni * 8 + 2 * tig;
            const float c0 = b1p[gn] + b2p[gn];
            const float c1 = b1p[gn + 1] + b2p[gn + 1];
            *(float2*)&xp[((size_t)sA * B_ + bb) * G4 + gn] =
                make_float2(fmaf(acc[mi][ni][0], DSC, c0), fmaf(acc[mi][ni][1], DSC, c1));
            *(float2*)&xp[((size_t)(sA + 8) * B_ + bb) * G4 + gn] =
                make_float2(fmaf(acc[mi][ni][2], DSC, c0), fmaf(acc[mi][ni][3], DSC, c1));
        }
    }
}

__device__ __forceinline__ float sigmf(float x) { return 1.0f / (1.0f + expf(-x)); }

__device__ __forceinline__ unsigned ld_acq(const unsigned* p) {
    unsigned v;
    asm volatile("ld.global.acquire.gpu.u32 %0, [%1];" : "=r"(v) : "l"(p));
    return v;
}
__device__ __forceinline__ void st_rel(unsigned* p, unsigned v) {
    asm volatile("st.global.release.gpu.u32 [%0], %1;" :: "l"(p), "r"(v));
}
// Round-7-proven barrier: atomic arrival + generation release + acquire poll.
__device__ __forceinline__ void dir_bar(int d, unsigned tgt) {
    __syncthreads();
    if (threadIdx.x == 0) {
        __threadfence();
        unsigned arr = atomicAdd(&g_cnt[d], 1u) + 1u;
        if (arr == 64u * tgt) st_rel(&g_gen2[d], tgt);
        else while (ld_acq(&g_gen2[d]) < tgt) __nanosleep(32);
    }
    __syncthreads();
}

// 128 persistent blocks, 256 threads; dir = blk>>6; block owns 8 hidden units
// (32 gate cols). C[64x32] = h[64x512] @ Whslice per step, fp16x2-split MMA.
extern "C" __global__ void __launch_bounds__(256, 1)
lstm_recur(const float* __restrict__ sent, float* __restrict__ out,
           const float* __restrict__ Wh_f, const float* __restrict__ Wh_b) {
    const int blk = blockIdx.x, d = blk >> 6, grp = blk & 63, u0 = grp * 8;
    const float* __restrict__ Wh = d ? Wh_b : Wh_f;
    const float* __restrict__ xp = g_xp[d];

    extern __shared__ unsigned smr[];
    uint4* Bs = (uint4*)smr;                    // [32 ks][4 nt][32 lane] {b0h,b1h,b0l,b1l}
    float* gbp = (float*)(Bs + 32 * 4 * 32);    // [2][64][GBP_LD]

    const int tid = threadIdx.x;
    const int wid = tid >> 5, lane = tid & 31;
    const int gid = lane >> 2, tig = lane & 3;
    const int mt = wid & 3, khw = wid >> 2;

    // pack Wh slice (scaled) into B-fragment order, once
    for (int i = tid; i < 32 * 4 * 32; i += 256) {
        const int ks = i >> 7, nt = (i >> 5) & 3, ln = i & 31;
        const int g = ln >> 2, t2 = ln & 3;
        const int col = nt * H_ + u0 + g;
        const int k0 = ks * 16;
        uint4 v;
        hsplit2(Wh[(size_t)(k0 + 2 * t2) * G4 + col] * SC,
                Wh[(size_t)(k0 + 2 * t2 + 1) * G4 + col] * SC, v.x, v.z);
        hsplit2(Wh[(size_t)(k0 + 8 + 2 * t2) * G4 + col] * SC,
                Wh[(size_t)(k0 + 9 + 2 * t2) * G4 + col] * SC, v.y, v.w);
        Bs[i] = v;
    }
    if (tid < 128) g_A[d][0][grp * 128 + tid] = make_uint4(0u, 0u, 0u, 0u);
    unsigned barno = 1;
    dir_bar(d, barno);

    // cell-update mapping: thread -> (batch cb, units ue, ue+1)
    const int cb = tid >> 2, ue = (tid & 3) * 2;
    // producer h-fragment slot constants
    const int kstep_p = grp >> 1, half = grp & 1;
    const int mtb = cb >> 4, rh = (cb >> 3) & 1, gb = cb & 7, tb = tid & 3;
    const int pslot = ((kstep_p * 4 + mtb) * 32 + gb * 4 + tb) * 2;
    const float* __restrict__ sent_b = sent + (size_t)cb * S_;
    float cv0 = 0.f, cv1 = 0.f;

    for (int t = 0; t < S_; ++t) {
        const int tt = d ? (S_ - 1 - t) : t;
        const uint4* __restrict__ Ab = g_A[d][t & 1];
        const int wbuf = 1 - (t & 1);

        // prefetch this step's input-projection gates + sentiment
        const float* xb = xp + ((size_t)tt * B_ + cb) * G4 + u0 + ue;
        const float2 pxi = *(const float2*)(xb);
        const float2 pxf = *(const float2*)(xb + H_);
        const float2 pxg = *(const float2*)(xb + 2 * H_);
        const float2 pxo = *(const float2*)(xb + 3 * H_);
        const float st = sent_b[tt];

        float acc[4][4];
#pragma unroll
        for (int nt = 0; nt < 4; ++nt)
#pragma unroll
            for (int j = 0; j < 4; ++j) acc[nt][j] = 0.f;

        int sl = (((khw * 16) * 4 + mt) * 32 + lane) * 2;
        uint4 nah = __ldcg(&Ab[sl]);
        uint4 nal = __ldcg(&Ab[sl + 1]);
#pragma unroll 4
        for (int ksl = 0; ksl < 16; ++ksl) {
            const uint4 ah = nah, al = nal;
            if (ksl < 15) {
                const int ns = (((khw * 16 + ksl + 1) * 4 + mt) * 32 + lane) * 2;
                nah = __ldcg(&Ab[ns]);
                nal = __ldcg(&Ab[ns + 1]);
            }
            const uint4* bp = &Bs[((khw * 16 + ksl) * 4) * 32 + lane];
#pragma unroll
            for (int nt = 0; nt < 4; ++nt) {
                const uint4 bb = bp[nt * 32];
                mma_f16u(acc[nt], ah, bb.x, bb.y);   // hi*hi
                mma_f16u(acc[nt], ah, bb.z, bb.w);   // hi*lo
                mma_f16u(acc[nt], al, bb.x, bb.y);   // lo*hi
            }
        }
        {
            float* gp = gbp + khw * (64 * GBP_LD);
            const int r0 = mt * 16 + gid;
#pragma unroll
            for (int nt = 0; nt < 4; ++nt) {
                *(float2*)&gp[r0 * GBP_LD + nt * 8 + 2 * tig] =
                    make_float2(acc[nt][0], acc[nt][1]);
                *(float2*)&gp[(r0 + 8) * GBP_LD + nt * 8 + 2 * tig] =
                    make_float2(acc[nt][2], acc[nt][3]);
            }
        }
        __syncthreads();

        // cell update: 2 units per thread; partials descaled by 2^-16
        {
            const float* q0 = gbp + cb * GBP_LD;
            const float* q1 = q0 + 64 * GBP_LD;
            const float2 ia = *(const float2*)(q0 + ue),      ib = *(const float2*)(q1 + ue);
            const float2 fa = *(const float2*)(q0 + 8 + ue),  fb = *(const float2*)(q1 + 8 + ue);
            const float2 ga = *(const float2*)(q0 + 16 + ue), gbv = *(const float2*)(q1 + 16 + ue);
            const float2 oa = *(const float2*)(q0 + 24 + ue), ob = *(const float2*)(q1 + 24 + ue);
            const float xi0 = fmaf(ia.x + ib.x, DSC, pxi.x);
            const float xi1 = fmaf(ia.y + ib.y, DSC, pxi.y);
            const float xf0 = fmaf(fa.x + fb.x, DSC, pxf.x);
            const float xf1 = fmaf(fa.y + fb.y, DSC, pxf.y);
            const float xg0 = fmaf(ga.x + gbv.x, DSC, pxg.x);
            const float xg1 = fmaf(ga.y + gbv.y, DSC, pxg.y);
            const float xo0 = fmaf(oa.x + ob.x, DSC, pxo.x);
            const float xo1 = fmaf(oa.y + ob.y, DSC, pxo.y);
            cv0 = sigmf(xf0) * (1.0f + st) * cv0 + sigmf(xi0) * st * tanhf(xg0);
            cv1 = sigmf(xf1) * (1.0f + st) * cv1 + sigmf(xi1) * st * tanhf(xg1);
            const float hv0 = sigmf(xo0) * tanhf(cv0);
            const float hv1 = sigmf(xo1) * tanhf(cv1);
            *(float2*)&out[((size_t)cb * S_ + tt) * (2 * H_) + d * H_ + u0 + ue] =
                make_float2(hv0, hv1);
            unsigned whi, wlo;
            hsplit2(hv0 * SC, hv1 * SC, whi, wlo);
            unsigned* bas = (unsigned*)&g_A[d][wbuf][pslot];
            bas[half * 2 + rh] = whi;
            bas[4 + half * 2 + rh] = wlo;
        }
        ++barno;
        dir_bar(d, barno);
    }
}

extern "C" void kernel_launch(void* const* d_in, const int* in_sizes, int n_in,
                              void* d_out, int out_size) {
    const float* x    = (const float*)d_in[0];
    const float* sent = (const float*)d_in[1];
    const float* Wi_f = (const float*)d_in[2];
    const float* bi_f = (const float*)d_in[3];
    const float* Wh_f = (const float*)d_in[4];
    const float* bh_f = (const float*)d_in[5];
    const float* Wi_b = (const float*)d_in[6];
    const float* bi_b = (const float*)d_in[7];
    const float* Wh_b = (const float*)d_in[8];
    const float* bh_b = (const float*)d_in[9];
    float* out = (float*)d_out;

    static bool attr_done = false;
    if (!attr_done) {
        cudaFuncSetAttribute(lstm_recur, cudaFuncAttributeMaxDynamicSharedMemorySize,
                             REC_SMEM);
        cudaFuncSetAttribute(xproj_gemm, cudaFuncAttributeMaxDynamicSharedMemorySize,
                             GEMM_SMEM);
        attr_done = true;
    }

    dim3 ggrid(G4 / BN, (B_ * S_) / BM, 2);
    xproj_gemm<<<ggrid, 256, GEMM_SMEM>>>(x, Wi_f, bi_f, bh_f, Wi_b, bi_b, bh_b);
    init_sync_kernel<<<1, 1>>>();
    lstm_recur<<<128, 256, REC_SMEM>>>(sent, out, Wh_f, Wh_b);
}